// round 1
// baseline (speedup 1.0000x reference)
#include <cuda_runtime.h>
#include <cstdint>

#define BB 16
#define DD 40
#define NN 64512
#define KK 4
#define TPB 256
#define NBLK (NN / TPB)          // 252
#define ROW (KK * DD + KK)       // 164 floats per batch: 160 U/V_Y + 4 u2/sumY
#define ALPHA_F 5.0f

// Scratch (no allocations allowed): centroids + accumulators
__device__ float g_U[BB * ROW];    // per batch: U[k][d] (160) then u2[k] (4)
__device__ float g_acc[BB * ROW];  // per batch: V_Y[k][d] (160) then sumY[k] (4)

// ---------------------------------------------------------------------------
// init: detect idx dtype, gather U0 = tanh(V[b, :, idx]) , compute u2, zero acc
// ---------------------------------------------------------------------------
__global__ void init_kernel(const float* __restrict__ V, const void* __restrict__ idx_raw) {
    __shared__ int is64;
    const int t = threadIdx.x;  // 64 threads, one per (b,k)
    if (t == 0) {
        // Only inspect first 64 ints (256B) — safe for both int32 and int64 buffers.
        // If int64 little-endian, odd int32 words are the (zero) high halves.
        const int* p = (const int*)idx_raw;
        int all0 = 1;
        for (int i = 1; i < 64; i += 2) {
            if (p[i] != 0) { all0 = 0; break; }
        }
        is64 = all0;
    }
    __syncthreads();

    // zero accumulators for the first km iteration
    for (int i = t; i < BB * ROW; i += 64) g_acc[i] = 0.0f;

    long long idxv;
    if (is64) idxv = ((const long long*)idx_raw)[t];
    else      idxv = (long long)((const int*)idx_raw)[t];

    const int b = t / KK;
    const int k = t % KK;
    const float* vb = V + (size_t)b * DD * NN;
    float u2 = 0.0f;
    for (int d = 0; d < DD; d++) {
        float u = tanhf(vb[(size_t)d * NN + (size_t)idxv]);
        g_U[b * ROW + k * DD + d] = u;
        u2 += u * u;
    }
    g_U[b * ROW + KK * DD + k] = u2;
}

// ---------------------------------------------------------------------------
// km iteration: soft assignment + weighted accumulation.
// FIRST=true: src is raw V, apply tanh and write Vact to output buffer.
// ---------------------------------------------------------------------------
template <bool FIRST>
__global__ __launch_bounds__(TPB) void km_kernel(const float* __restrict__ src,
                                                 float* __restrict__ vact_out) {
    const int b = blockIdx.y;
    const int t = threadIdx.x;
    const int n = blockIdx.x * TPB + t;

    __shared__ float sU[KK * DD];
    __shared__ float su2[KK];
    __shared__ float sV[DD][TPB];   // 40 KB: points staged for the d-major reduction
    __shared__ float sY[KK][TPB];   // 4 KB : soft assignments

    if (t < KK * DD) sU[t] = g_U[b * ROW + t];
    if (t >= KK * DD && t < KK * DD + KK) su2[t - KK * DD] = g_U[b * ROW + t];
    __syncthreads();

    const float* vp = src + (size_t)b * DD * NN + n;
    float v2 = 0.0f;
    float dot[KK] = {0.f, 0.f, 0.f, 0.f};
#pragma unroll
    for (int d = 0; d < DD; d++) {
        float v = vp[(size_t)d * NN];
        if (FIRST) {
            v = tanhf(v);
            vact_out[(size_t)b * DD * NN + (size_t)d * NN + n] = v;
        }
        sV[d][t] = v;
        v2 += v * v;
#pragma unroll
        for (int k = 0; k < KK; k++) dot[k] += v * sU[k * DD + d];
    }

    // dist = -alpha * sqrt(max(v2 + u2 - 2 dot, 1e-12)); softmax over k
    float dist[KK];
    float m = -1e30f;
#pragma unroll
    for (int k = 0; k < KK; k++) {
        float d2 = fmaxf(v2 + su2[k] - 2.0f * dot[k], 1e-12f);
        dist[k] = -ALPHA_F * sqrtf(d2);
        m = fmaxf(m, dist[k]);
    }
    float e[KK], s = 0.0f;
#pragma unroll
    for (int k = 0; k < KK; k++) { e[k] = expf(dist[k] - m); s += e[k]; }
    const float inv = 1.0f / s;
#pragma unroll
    for (int k = 0; k < KK; k++) sY[k][t] = e[k] * inv;
    __syncthreads();

    // Block reduction: warp w owns d in [5w, 5w+5); each lane strides points.
    const int w = t >> 5;
    const int l = t & 31;
    float acc[5][KK];
#pragma unroll
    for (int j = 0; j < 5; j++)
#pragma unroll
        for (int k = 0; k < KK; k++) acc[j][k] = 0.0f;

#pragma unroll
    for (int i = 0; i < TPB / 32; i++) {
        const int p = l + i * 32;
        const float y0 = sY[0][p], y1 = sY[1][p], y2 = sY[2][p], y3 = sY[3][p];
#pragma unroll
        for (int j = 0; j < 5; j++) {
            const float v = sV[w * 5 + j][p];
            acc[j][0] += y0 * v;
            acc[j][1] += y1 * v;
            acc[j][2] += y2 * v;
            acc[j][3] += y3 * v;
        }
    }
#pragma unroll
    for (int j = 0; j < 5; j++)
#pragma unroll
        for (int k = 0; k < KK; k++)
#pragma unroll
            for (int off = 16; off > 0; off >>= 1)
                acc[j][k] += __shfl_down_sync(0xffffffffu, acc[j][k], off);

    if (l == 0) {
#pragma unroll
        for (int j = 0; j < 5; j++)
#pragma unroll
            for (int k = 0; k < KK; k++)
                atomicAdd(&g_acc[b * ROW + k * DD + (w * 5 + j)], acc[j][k]);
    }

    // sumY reduced by warp 0
    if (w == 0) {
        float sy[KK] = {0.f, 0.f, 0.f, 0.f};
#pragma unroll
        for (int i = 0; i < TPB / 32; i++) {
            const int p = l + i * 32;
#pragma unroll
            for (int k = 0; k < KK; k++) sy[k] += sY[k][p];
        }
#pragma unroll
        for (int k = 0; k < KK; k++)
#pragma unroll
            for (int off = 16; off > 0; off >>= 1)
                sy[k] += __shfl_down_sync(0xffffffffu, sy[k], off);
        if (l == 0) {
#pragma unroll
            for (int k = 0; k < KK; k++)
                atomicAdd(&g_acc[b * ROW + KK * DD + k], sy[k]);
        }
    }
}

// ---------------------------------------------------------------------------
// normalize: U = V_Y / (sumY + 1e-9), recompute u2, re-zero accumulators.
// Optionally writes A to the output buffer (last iteration).
// ---------------------------------------------------------------------------
__global__ void norm_kernel(float* __restrict__ outA, int writeA) {
    const int t = threadIdx.x;  // 256 threads, 1 block
    for (int i = t; i < BB * KK * DD; i += 256) {
        const int b = i / (KK * DD);
        const int r = i % (KK * DD);
        const int k = r / DD;
        const float u = g_acc[b * ROW + r] / (g_acc[b * ROW + KK * DD + k] + 1e-9f);
        g_U[b * ROW + r] = u;
        if (writeA) outA[i] = u;
    }
    __syncthreads();
    if (t < BB * KK) {
        const int b = t / KK;
        const int k = t % KK;
        float u2 = 0.0f;
        for (int d = 0; d < DD; d++) {
            const float u = g_U[b * ROW + k * DD + d];
            u2 += u * u;
        }
        g_U[b * ROW + KK * DD + k] = u2;
    }
    for (int i = t; i < BB * ROW; i += 256) g_acc[i] = 0.0f;
}

// ---------------------------------------------------------------------------
// final mask: dist = A . Vact (dot product), softmax over K
// ---------------------------------------------------------------------------
__global__ __launch_bounds__(TPB) void mask_kernel(const float* __restrict__ vact,
                                                   float* __restrict__ mask) {
    const int b = blockIdx.y;
    const int t = threadIdx.x;
    const int n = blockIdx.x * TPB + t;

    __shared__ float sA[KK * DD];
    if (t < KK * DD) sA[t] = g_U[b * ROW + t];
    __syncthreads();

    const float* vp = vact + (size_t)b * DD * NN + n;
    float dot[KK] = {0.f, 0.f, 0.f, 0.f};
#pragma unroll
    for (int d = 0; d < DD; d++) {
        const float v = vp[(size_t)d * NN];
#pragma unroll
        for (int k = 0; k < KK; k++) dot[k] += v * sA[k * DD + d];
    }
    float m = -1e30f;
#pragma unroll
    for (int k = 0; k < KK; k++) m = fmaxf(m, dot[k]);
    float e[KK], s = 0.0f;
#pragma unroll
    for (int k = 0; k < KK; k++) { e[k] = expf(dot[k] - m); s += e[k]; }
    const float inv = 1.0f / s;
#pragma unroll
    for (int k = 0; k < KK; k++)
        mask[(size_t)b * KK * NN + (size_t)k * NN + n] = e[k] * inv;
}

// ---------------------------------------------------------------------------
extern "C" void kernel_launch(void* const* d_in, const int* in_sizes, int n_in,
                              void* d_out, int out_size) {
    const float* V = (const float*)d_in[0];
    const void* idx = d_in[1];

    float* out = (float*)d_out;
    float* mask = out;                                   // (B, K, N)
    float* vact = out + (size_t)BB * KK * NN;            // (B, D, N)
    float* outA = vact + (size_t)BB * DD * NN;           // (B, K, D)

    init_kernel<<<1, 64>>>(V, idx);

    dim3 grid(NBLK, BB);
    for (int it = 0; it < 10; it++) {
        if (it == 0) km_kernel<true><<<grid, TPB>>>(V, vact);
        else         km_kernel<false><<<grid, TPB>>>(vact, nullptr);
        norm_kernel<<<1, 256>>>(outA, it == 9 ? 1 : 0);
    }
    mask_kernel<<<grid, TPB>>>(vact, mask);
}

// round 2
// speedup vs baseline: 2.1757x; 2.1757x over previous
#include <cuda_runtime.h>
#include <cuda_fp16.h>
#include <cstdint>

#define BB 16
#define DD 40
#define NN 64512
#define KK 4
#define TPB 256
#define PTS (2 * TPB)            // 512 points per block (2 per thread)
#define NBLK (NN / PTS)          // 126
#define ROW (KK * DD + KK)       // 164: V_Y[k][d] (160) then sumY[k] (4)
#define ALPHA_F 5.0f

// Scratch (__device__ globals: the sanctioned no-alloc workaround)
__device__ float  g_U[BB * ROW];          // init centroids: U (160) + u2 (4) per batch
__device__ float  g_acc[3][BB * ROW];     // triple-buffered accumulators
__device__ __half g_Vh[(size_t)BB * DD * NN];  // 82.6 MB fp16 shadow of Vact (L2-resident)

// ---------------------------------------------------------------------------
// init: detect idx dtype, gather U0 = tanh(V[b,:,idx]), compute u2, zero buf0
// ---------------------------------------------------------------------------
__global__ void init_kernel(const float* __restrict__ V, const void* __restrict__ idx_raw) {
    __shared__ int is64;
    const int t = threadIdx.x;  // 64 threads, one per (b,k)
    if (t == 0) {
        const int* p = (const int*)idx_raw;   // first 256B safe for either dtype
        int all0 = 1;
        for (int i = 1; i < 64; i += 2)
            if (p[i] != 0) { all0 = 0; break; }
        is64 = all0;
    }
    __syncthreads();

    for (int i = t; i < BB * ROW; i += 64) g_acc[0][i] = 0.0f;

    long long idxv;
    if (is64) idxv = ((const long long*)idx_raw)[t];
    else      idxv = (long long)((const int*)idx_raw)[t];

    const int b = t / KK;
    const int k = t % KK;
    const float* vb = V + (size_t)b * DD * NN;
    float u2 = 0.0f;
    for (int d = 0; d < DD; d++) {
        float u = tanhf(vb[(size_t)d * NN + (size_t)idxv]);
        g_U[b * ROW + k * DD + d] = u;
        u2 += u * u;
    }
    g_U[b * ROW + KK * DD + k] = u2;
}

// ---------------------------------------------------------------------------
// km iteration. MODE 0: read raw V (fp32), apply tanh, emit Vact fp32 + fp16
//               shadow; centroids from g_U.
// MODE 1: read fp16 shadow (L2-resident); centroids from g_acc[srcIdx].
// Every block also zeroes g_acc[zeroIdx] (idempotent races) -> no norm kernel.
// ---------------------------------------------------------------------------
template <int MODE>
__global__ __launch_bounds__(TPB) void km_kernel(const float* __restrict__ V,
                                                 float* __restrict__ vact,
                                                 int srcIdx, int dstIdx, int zeroIdx) {
    const int b = blockIdx.y;
    const int t = threadIdx.x;

    __shared__ float   sU[KK * DD];
    __shared__ float   su2[KK];
    __shared__ __half2 sV[DD][TPB];
    __shared__ __half2 sY[KK][TPB];

    if (MODE == 0) {
        if (t < KK * DD) sU[t] = g_U[b * ROW + t];
        if (t < KK)      su2[t] = g_U[b * ROW + KK * DD + t];
    } else {
        if (t < KK * DD) {
            const int k = t / DD;
            const float* src = g_acc[srcIdx] + b * ROW;
            sU[t] = src[t] / (src[KK * DD + k] + 1e-9f);
        }
    }
    if (t < ROW) g_acc[zeroIdx][b * ROW + t] = 0.0f;
    __syncthreads();
    if (MODE == 1) {
        if (t < KK) {
            float s = 0.0f;
            for (int d = 0; d < DD; d++) { float u = sU[t * DD + d]; s += u * u; }
            su2[t] = s;
        }
        __syncthreads();
    }

    const int n0 = blockIdx.x * PTS + 2 * t;
    float v2a = 0.f, v2b = 0.f;
    float dota[KK] = {0.f, 0.f, 0.f, 0.f};
    float dotb[KK] = {0.f, 0.f, 0.f, 0.f};

    if (MODE == 0) {
        const float* vp = V + (size_t)b * DD * NN + n0;
        float* wp = vact + (size_t)b * DD * NN + n0;
        __half* hp = g_Vh + (size_t)b * DD * NN + n0;
#pragma unroll 8
        for (int d = 0; d < DD; d++) {
            float2 f = *(const float2*)(vp + (size_t)d * NN);
            f.x = tanhf(f.x); f.y = tanhf(f.y);
            *(float2*)(wp + (size_t)d * NN) = f;
            __half2 h = __floats2half2_rn(f.x, f.y);
            *(__half2*)(hp + (size_t)d * NN) = h;
            sV[d][t] = h;
            v2a += f.x * f.x; v2b += f.y * f.y;
#pragma unroll
            for (int k = 0; k < KK; k++) {
                const float u = sU[k * DD + d];
                dota[k] += f.x * u; dotb[k] += f.y * u;
            }
        }
    } else {
        const __half2* vp = (const __half2*)(g_Vh + (size_t)b * DD * NN) + (n0 >> 1);
#pragma unroll
        for (int d = 0; d < DD; d++) {
            const __half2 h = vp[d * (NN / 2)];
            const float2 f = __half22float2(h);
            sV[d][t] = h;
            v2a += f.x * f.x; v2b += f.y * f.y;
#pragma unroll
            for (int k = 0; k < KK; k++) {
                const float u = sU[k * DD + d];
                dota[k] += f.x * u; dotb[k] += f.y * u;
            }
        }
    }

    // softmax over k of -alpha*sqrt(max(v2+u2-2dot, 1e-12)) for both points
    float ya[KK], yb[KK];
    {
        float da[KK], db[KK];
        float ma = -1e30f, mb = -1e30f;
#pragma unroll
        for (int k = 0; k < KK; k++) {
            da[k] = -ALPHA_F * sqrtf(fmaxf(v2a + su2[k] - 2.0f * dota[k], 1e-12f));
            db[k] = -ALPHA_F * sqrtf(fmaxf(v2b + su2[k] - 2.0f * dotb[k], 1e-12f));
            ma = fmaxf(ma, da[k]); mb = fmaxf(mb, db[k]);
        }
        float sa = 0.f, sb = 0.f;
#pragma unroll
        for (int k = 0; k < KK; k++) {
            ya[k] = __expf(da[k] - ma); sa += ya[k];
            yb[k] = __expf(db[k] - mb); sb += yb[k];
        }
        const float ia = 1.0f / sa, ib = 1.0f / sb;
#pragma unroll
        for (int k = 0; k < KK; k++) sY[k][t] = __floats2half2_rn(ya[k] * ia, yb[k] * ib);
    }
    __syncthreads();

    // block reduction: warp w owns d-rows [5w, 5w+5); lanes stride the 256 slots
    const int w = t >> 5;
    const int l = t & 31;
    float acc[5][KK];
#pragma unroll
    for (int j = 0; j < 5; j++)
#pragma unroll
        for (int k = 0; k < KK; k++) acc[j][k] = 0.0f;
    float sy[KK] = {0.f, 0.f, 0.f, 0.f};

#pragma unroll
    for (int i = 0; i < TPB / 32; i++) {
        const int p = l + 32 * i;
        float2 y[KK];
#pragma unroll
        for (int k = 0; k < KK; k++) y[k] = __half22float2(sY[k][p]);
        if (w == 0) {
#pragma unroll
            for (int k = 0; k < KK; k++) sy[k] += y[k].x + y[k].y;
        }
#pragma unroll
        for (int j = 0; j < 5; j++) {
            const float2 vf = __half22float2(sV[w * 5 + j][p]);
#pragma unroll
            for (int k = 0; k < KK; k++)
                acc[j][k] += y[k].x * vf.x + y[k].y * vf.y;
        }
    }
#pragma unroll
    for (int j = 0; j < 5; j++)
#pragma unroll
        for (int k = 0; k < KK; k++)
#pragma unroll
            for (int off = 16; off > 0; off >>= 1)
                acc[j][k] += __shfl_down_sync(0xffffffffu, acc[j][k], off);
    if (w == 0)
#pragma unroll
        for (int k = 0; k < KK; k++)
#pragma unroll
            for (int off = 16; off > 0; off >>= 1)
                sy[k] += __shfl_down_sync(0xffffffffu, sy[k], off);

    float* dst = g_acc[dstIdx] + b * ROW;
    if (l == 0) {
#pragma unroll
        for (int j = 0; j < 5; j++)
#pragma unroll
            for (int k = 0; k < KK; k++)
                atomicAdd(&dst[k * DD + (w * 5 + j)], acc[j][k]);
        if (w == 0)
#pragma unroll
            for (int k = 0; k < KK; k++) atomicAdd(&dst[KK * DD + k], sy[k]);
    }
}

// ---------------------------------------------------------------------------
// final: A = V_Y/(sumY+eps) from buf srcIdx; mask = softmax_k(A . Vact)
// reads fp32 Vact (exactness headroom); block x==0 writes A
// ---------------------------------------------------------------------------
__global__ __launch_bounds__(TPB) void mask_kernel(const float* __restrict__ vact,
                                                   float* __restrict__ mask,
                                                   float* __restrict__ outA,
                                                   int srcIdx) {
    const int b = blockIdx.y;
    const int t = threadIdx.x;

    __shared__ float sA[KK * DD];
    if (t < KK * DD) {
        const int k = t / DD;
        const float* src = g_acc[srcIdx] + b * ROW;
        const float a = src[t] / (src[KK * DD + k] + 1e-9f);
        sA[t] = a;
        if (blockIdx.x == 0) outA[b * KK * DD + t] = a;
    }
    __syncthreads();

    const int n0 = blockIdx.x * PTS + 2 * t;
    const float* vp = vact + (size_t)b * DD * NN + n0;
    float dota[KK] = {0.f, 0.f, 0.f, 0.f};
    float dotb[KK] = {0.f, 0.f, 0.f, 0.f};
#pragma unroll
    for (int d = 0; d < DD; d++) {
        const float2 f = *(const float2*)(vp + (size_t)d * NN);
#pragma unroll
        for (int k = 0; k < KK; k++) {
            const float a = sA[k * DD + d];
            dota[k] += f.x * a; dotb[k] += f.y * a;
        }
    }
    float ma = -1e30f, mb = -1e30f;
#pragma unroll
    for (int k = 0; k < KK; k++) { ma = fmaxf(ma, dota[k]); mb = fmaxf(mb, dotb[k]); }
    float ea[KK], eb[KK], sa = 0.f, sb = 0.f;
#pragma unroll
    for (int k = 0; k < KK; k++) {
        ea[k] = __expf(dota[k] - ma); sa += ea[k];
        eb[k] = __expf(dotb[k] - mb); sb += eb[k];
    }
    const float ia = 1.0f / sa, ib = 1.0f / sb;
#pragma unroll
    for (int k = 0; k < KK; k++) {
        float2 o; o.x = ea[k] * ia; o.y = eb[k] * ib;
        *(float2*)(mask + (size_t)b * KK * NN + (size_t)k * NN + n0) = o;
    }
}

// ---------------------------------------------------------------------------
extern "C" void kernel_launch(void* const* d_in, const int* in_sizes, int n_in,
                              void* d_out, int out_size) {
    const float* V = (const float*)d_in[0];
    const void* idx = d_in[1];

    float* out  = (float*)d_out;
    float* mask = out;                                 // (B, K, N)
    float* vact = out + (size_t)BB * KK * NN;          // (B, D, N)
    float* outA = vact + (size_t)BB * DD * NN;         // (B, K, D)

    init_kernel<<<1, 64>>>(V, idx);

    dim3 grid(NBLK, BB);
    for (int it = 0; it < 10; it++) {
        const int dstIdx  = it % 3;
        const int srcIdx  = (it + 2) % 3;
        const int zeroIdx = (it + 1) % 3;
        if (it == 0) km_kernel<0><<<grid, TPB>>>(V, vact, srcIdx, dstIdx, zeroIdx);
        else         km_kernel<1><<<grid, TPB>>>(nullptr, nullptr, srcIdx, dstIdx, zeroIdx);
    }
    // after it=9, accumulators live in buffer 0
    mask_kernel<<<grid, TPB>>>(vact, mask, outA, 0);
}

// round 3
// speedup vs baseline: 3.2004x; 1.4710x over previous
#include <cuda_runtime.h>
#include <cuda_fp16.h>
#include <cstdint>

#define BB 16
#define DD 40
#define DPAD 48
#define NN 64512
#define KK 4
#define TPB 256
#define PTSB 256                  // points per km block
#define NBLK (NN / PTSB)          // 252
#define ROW (KK * DD + KK)        // 164
#define ALPHA_F 5.0f
#define PITCH 264                 // halves per sV/sY row = 528B (row offsets distinct mod 128 -> ldsm conflict-free)
#define UPITCH 56                 // sU row pitch (112B)

// Scratch (__device__ globals: sanctioned no-alloc workaround)
__device__ float  g_acc[3][BB * ROW];          // triple-buffered centroid accumulators
__device__ __half g_Vh[(size_t)BB * DD * NN];  // fp16 shadow of Vact
__device__ float  g_v2[(size_t)BB * NN];       // per-point ||v||^2 (iteration-invariant, fp32)

// ---------------------------------------------------------------------------
// PTX helpers
// ---------------------------------------------------------------------------
__device__ __forceinline__ uint32_t smem_u32(const void* p) {
    uint32_t a;
    asm("{ .reg .u64 t; cvta.to.shared.u64 t, %1; cvt.u32.u64 %0, t; }" : "=r"(a) : "l"(p));
    return a;
}
__device__ __forceinline__ void ldsm_x4(uint32_t* r, uint32_t a) {
    asm volatile("ldmatrix.sync.aligned.m8n8.x4.shared.b16 {%0,%1,%2,%3}, [%4];"
                 : "=r"(r[0]), "=r"(r[1]), "=r"(r[2]), "=r"(r[3]) : "r"(a));
}
__device__ __forceinline__ void ldsm_x2(uint32_t* r, uint32_t a) {
    asm volatile("ldmatrix.sync.aligned.m8n8.x2.shared.b16 {%0,%1}, [%2];"
                 : "=r"(r[0]), "=r"(r[1]) : "r"(a));
}
__device__ __forceinline__ void ldsm_x2_t(uint32_t* r, uint32_t a) {
    asm volatile("ldmatrix.sync.aligned.m8n8.x2.trans.shared.b16 {%0,%1}, [%2];"
                 : "=r"(r[0]), "=r"(r[1]) : "r"(a));
}
__device__ __forceinline__ void mma16816(float* c, const uint32_t* a, const uint32_t* b) {
    asm volatile("mma.sync.aligned.m16n8k16.row.col.f32.f16.f16.f32 "
                 "{%0,%1,%2,%3},{%4,%5,%6,%7},{%8,%9},{%0,%1,%2,%3};"
                 : "+f"(c[0]), "+f"(c[1]), "+f"(c[2]), "+f"(c[3])
                 : "r"(a[0]), "r"(a[1]), "r"(a[2]), "r"(a[3]), "r"(b[0]), "r"(b[1]));
}
__device__ __forceinline__ float tanh_fast(float x) {
    float e = __expf(fminf(2.0f * x, 80.0f));
    return 1.0f - __fdividef(2.0f, e + 1.0f);
}

// ---------------------------------------------------------------------------
// init: detect idx dtype; write U0 = tanh(V[b,:,idx]) into g_acc[2] in
// accumulator format (V_Y = u, sumY = 1); zero g_acc[0] (dst of iter 0).
// ---------------------------------------------------------------------------
__global__ void init_kernel(const float* __restrict__ V, const void* __restrict__ idx_raw) {
    __shared__ int is64;
    const int t = threadIdx.x;  // 64 threads, one per (b,k)
    if (t == 0) {
        const int* p = (const int*)idx_raw;   // first 256B safe for either dtype
        int all0 = 1;
        for (int i = 1; i < 64; i += 2)
            if (p[i] != 0) { all0 = 0; break; }
        is64 = all0;
    }
    __syncthreads();

    for (int i = t; i < BB * ROW; i += 64) g_acc[0][i] = 0.0f;

    long long idxv;
    if (is64) idxv = ((const long long*)idx_raw)[t];
    else      idxv = (long long)((const int*)idx_raw)[t];

    const int b = t / KK;
    const int k = t % KK;
    const float* vb = V + (size_t)b * DD * NN;
    for (int d = 0; d < DD; d++)
        g_acc[2][b * ROW + k * DD + d] = tanhf(vb[(size_t)d * NN + (size_t)idxv]);
    g_acc[2][b * ROW + KK * DD + k] = 1.0f;
}

// ---------------------------------------------------------------------------
// transform: Vact = tanh(V) (fp32 out), fp16 shadow, v2 = sum_d v^2 (fp32)
// 4 points/thread, float4 I/O. grid (63, 16)
// ---------------------------------------------------------------------------
__global__ __launch_bounds__(TPB) void transform_kernel(const float* __restrict__ V,
                                                        float* __restrict__ vact) {
    const int b = blockIdx.y;
    const int n0 = blockIdx.x * (TPB * 4) + 4 * threadIdx.x;
    const float* vp = V + (size_t)b * DD * NN + n0;
    float* wp = vact + (size_t)b * DD * NN + n0;
    __half* hp = g_Vh + (size_t)b * DD * NN + n0;

    float v2x = 0.f, v2y = 0.f, v2z = 0.f, v2w = 0.f;
#pragma unroll 8
    for (int d = 0; d < DD; d++) {
        float4 f = *(const float4*)(vp + (size_t)d * NN);
        f.x = tanh_fast(f.x); f.y = tanh_fast(f.y);
        f.z = tanh_fast(f.z); f.w = tanh_fast(f.w);
        *(float4*)(wp + (size_t)d * NN) = f;
        __half2 h01 = __floats2half2_rn(f.x, f.y);
        __half2 h23 = __floats2half2_rn(f.z, f.w);
        uint2 hh;
        hh.x = *(uint32_t*)&h01; hh.y = *(uint32_t*)&h23;
        *(uint2*)(hp + (size_t)d * NN) = hh;
        v2x += f.x * f.x; v2y += f.y * f.y; v2z += f.z * f.z; v2w += f.w * f.w;
    }
    float4 o; o.x = v2x; o.y = v2y; o.z = v2z; o.w = v2w;
    *(float4*)(g_v2 + (size_t)b * NN + n0) = o;
}

// ---------------------------------------------------------------------------
// km iteration, tensor-core version. One block = 256 points of one batch.
// phaseA: dot(Kpad16 x pts) = Upad(16x48) @ sV(48 x pts)     [3 ksteps]
// softmax -> sY (4 rows used of 16)
// phaseB: C2(16 x 48) = sYpad(16 x pts) @ sV^T(pts x 48)     [16 ksteps]
//         sV row 40 = ones  => C2[k][40] = sumY[k]
// ---------------------------------------------------------------------------
__global__ __launch_bounds__(TPB) void km_mma(int srcIdx, int dstIdx, int zeroIdx) {
    const int b = blockIdx.y;
    const int t = threadIdx.x;
    const int w = t >> 5;
    const int l = t & 31;
    const int n0 = blockIdx.x * PTSB;

    __shared__ __align__(16) __half sV[DPAD][PITCH];   // 25.3 KB
    __shared__ __align__(16) __half sY[16][PITCH];     // 8.4 KB
    __shared__ __align__(16) float  sDot[PTSB][KK];    // 4 KB
    __shared__ __align__(16) __half sU[16][UPITCH];    // 1.75 KB
    __shared__ float su2[KK];

    // -- prologue: normalize previous accumulators -> sU (half); pads; zero next buf
    const float* src = g_acc[srcIdx] + b * ROW;
    if (t < 160) {
        const int k = t / DD;
        const float u = src[t] / (src[KK * DD + k] + 1e-9f);
        sU[k][t - k * DD] = __float2half(u);
    }
    if (t < 32) sU[t >> 3][DD + (t & 7)] = __float2half(0.0f);  // rows 0-3, cols 40-47 = 0
    if (t < ROW) g_acc[zeroIdx][b * ROW + t] = 0.0f;
    // sV pad rows: row 40 = ones (sumY column), rows 41-47 = 0
    sV[40][t] = __float2half(1.0f);
#pragma unroll
    for (int r = 41; r < DPAD; r++) sV[r][t] = __float2half(0.0f);

    // -- stage points: 10 x LDG.64 (4 halves) per thread
    const __half* gv = g_Vh + (size_t)b * DD * NN + n0;
#pragma unroll
    for (int i = 0; i < (DD * PTSB / 4) / TPB; i++) {   // 10
        const int idx = t + i * TPB;
        const int d = idx >> 6, q = idx & 63;
        const uint2 val = *(const uint2*)(gv + (size_t)d * NN + 4 * q);
        *(uint2*)(&sV[d][4 * q]) = val;
    }
    const float v2 = g_v2[(size_t)b * NN + n0 + t];

    __syncthreads();

    // -- phaseA
    {
        const uint32_t smU = smem_u32(&sU[0][0]);
        const uint32_t smV = smem_u32(&sV[0][0]);
        float c[4][4];
#pragma unroll
        for (int j = 0; j < 4; j++)
#pragma unroll
            for (int x = 0; x < 4; x++) c[j][x] = 0.0f;
#pragma unroll
        for (int ks = 0; ks < 3; ks++) {
            uint32_t a[4];
            ldsm_x4(a, smU + (uint32_t)((l & 15) * (UPITCH * 2) + (l >> 4) * 16 + ks * 32));
#pragma unroll
            for (int j = 0; j < 4; j++) {
                const int nt = 4 * w + j;
                uint32_t bb[2];
                ldsm_x2_t(bb, smV + (uint32_t)((16 * ks + (l & 15)) * (PITCH * 2) + nt * 16));
                mma16816(c[j], a, bb);
            }
        }
        if (l < 16) {
            const int r = l >> 2;
#pragma unroll
            for (int j = 0; j < 4; j++) {
                const int pt = 8 * (4 * w + j) + 2 * (l & 3);
                sDot[pt][r]     = c[j][0];
                sDot[pt + 1][r] = c[j][1];
            }
        }
    }
    // su2 from half-rounded U (consistent with the MMA's U)
    if (t < KK) {
        float s = 0.0f;
        for (int d = 0; d < DD; d++) { const float u = __half2float(sU[t][d]); s += u * u; }
        su2[t] = s;
    }
    __syncthreads();

    // -- softmax over k (one point per thread)
    {
        const float4 dk = *(const float4*)&sDot[t][0];
        float dist[KK];
        dist[0] = -ALPHA_F * sqrtf(fmaxf(v2 + su2[0] - 2.0f * dk.x, 1e-12f));
        dist[1] = -ALPHA_F * sqrtf(fmaxf(v2 + su2[1] - 2.0f * dk.y, 1e-12f));
        dist[2] = -ALPHA_F * sqrtf(fmaxf(v2 + su2[2] - 2.0f * dk.z, 1e-12f));
        dist[3] = -ALPHA_F * sqrtf(fmaxf(v2 + su2[3] - 2.0f * dk.w, 1e-12f));
        float m = fmaxf(fmaxf(dist[0], dist[1]), fmaxf(dist[2], dist[3]));
        float e[KK], s = 0.0f;
#pragma unroll
        for (int k = 0; k < KK; k++) { e[k] = __expf(dist[k] - m); s += e[k]; }
        const float inv = 1.0f / s;
#pragma unroll
        for (int k = 0; k < KK; k++) sY[k][t] = __float2half(e[k] * inv);
    }
    __syncthreads();

    // -- phaseB (C2 kept in regs across the aliasing barrier)
    {
        const uint32_t smY = smem_u32(&sY[0][0]);
        const uint32_t smV = smem_u32(&sV[0][0]);
        float c2[6][4];
#pragma unroll
        for (int j = 0; j < 6; j++)
#pragma unroll
            for (int x = 0; x < 4; x++) c2[j][x] = 0.0f;
#pragma unroll
        for (int s = 0; s < 2; s++) {
            const int ks = 2 * w + s;            // pts chunk [16ks, 16ks+16)
            uint32_t a[4];
            ldsm_x4(a, smY + (uint32_t)((l & 15) * (PITCH * 2) + (l >> 4) * 16 + ks * 32));
#pragma unroll
            for (int nt = 0; nt < 6; nt++) {     // d chunk [8nt, 8nt+8)
                uint32_t bb[2];
                ldsm_x2(bb, smV + (uint32_t)((8 * nt + (l & 7)) * (PITCH * 2)
                                             + (16 * ks + 8 * ((l >> 3) & 1)) * 2));
                mma16816(c2[nt], a, bb);
            }
        }
        __syncthreads();
        // stage per-warp partials into sV alias: ptl[8][4][48] f32
        float* ptl = (float*)&sV[0][0];
        if (l < 16) {
            const int r = l >> 2, c0 = 2 * (l & 3);
#pragma unroll
            for (int nt = 0; nt < 6; nt++) {
                float2 p; p.x = c2[nt][0]; p.y = c2[nt][1];
                *(float2*)&ptl[w * 192 + r * 48 + 8 * nt + c0] = p;
            }
        }
        __syncthreads();
        // final reduce over 8 warps -> global atomics
        if (t < ROW) {
            const int r = t / 41, c = t % 41;
            float s = 0.0f;
#pragma unroll
            for (int ww = 0; ww < 8; ww++) s += ptl[ww * 192 + r * 48 + c];
            float* dst = g_acc[dstIdx] + b * ROW;
            if (c < DD) atomicAdd(&dst[r * DD + c], s);
            else        atomicAdd(&dst[KK * DD + r], s);
        }
    }
}

// ---------------------------------------------------------------------------
// final: A = V_Y/(sumY+eps); mask = softmax_k(A . Vact) from fp32 Vact
// ---------------------------------------------------------------------------
#define MPTS 512
#define MBLK (NN / MPTS)   // 126
__global__ __launch_bounds__(TPB) void mask_kernel(const float* __restrict__ vact,
                                                   float* __restrict__ mask,
                                                   float* __restrict__ outA,
                                                   int srcIdx) {
    const int b = blockIdx.y;
    const int t = threadIdx.x;

    __shared__ float sA[KK * DD];
    if (t < KK * DD) {
        const int k = t / DD;
        const float* src = g_acc[srcIdx] + b * ROW;
        const float a = src[t] / (src[KK * DD + k] + 1e-9f);
        sA[t] = a;
        if (blockIdx.x == 0) outA[b * KK * DD + t] = a;
    }
    __syncthreads();

    const int n0 = blockIdx.x * MPTS + 2 * t;
    const float* vp = vact + (size_t)b * DD * NN + n0;
    float dota[KK] = {0.f, 0.f, 0.f, 0.f};
    float dotb[KK] = {0.f, 0.f, 0.f, 0.f};
#pragma unroll
    for (int d = 0; d < DD; d++) {
        const float2 f = *(const float2*)(vp + (size_t)d * NN);
#pragma unroll
        for (int k = 0; k < KK; k++) {
            const float a = sA[k * DD + d];
            dota[k] += f.x * a; dotb[k] += f.y * a;
        }
    }
    float ma = -1e30f, mb = -1e30f;
#pragma unroll
    for (int k = 0; k < KK; k++) { ma = fmaxf(ma, dota[k]); mb = fmaxf(mb, dotb[k]); }
    float ea[KK], eb[KK], sa = 0.f, sb = 0.f;
#pragma unroll
    for (int k = 0; k < KK; k++) {
        ea[k] = __expf(dota[k] - ma); sa += ea[k];
        eb[k] = __expf(dotb[k] - mb); sb += eb[k];
    }
    const float ia = 1.0f / sa, ib = 1.0f / sb;
#pragma unroll
    for (int k = 0; k < KK; k++) {
        float2 o; o.x = ea[k] * ia; o.y = eb[k] * ib;
        *(float2*)(mask + (size_t)b * KK * NN + (size_t)k * NN + n0) = o;
    }
}

// ---------------------------------------------------------------------------
extern "C" void kernel_launch(void* const* d_in, const int* in_sizes, int n_in,
                              void* d_out, int out_size) {
    const float* V = (const float*)d_in[0];
    const void* idx = d_in[1];

    float* out  = (float*)d_out;
    float* mask = out;                                 // (B, K, N)
    float* vact = out + (size_t)BB * KK * NN;          // (B, D, N)
    float* outA = vact + (size_t)BB * DD * NN;         // (B, K, D)

    init_kernel<<<1, 64>>>(V, idx);
    transform_kernel<<<dim3(NN / (TPB * 4), BB), TPB>>>(V, vact);

    dim3 grid(NBLK, BB);
    for (int it = 0; it < 10; it++) {
        const int dstIdx  = it % 3;
        const int srcIdx  = (it + 2) % 3;   // it=0 reads g_acc[2] written by init
        const int zeroIdx = (it + 1) % 3;
        km_mma<<<grid, TPB>>>(srcIdx, dstIdx, zeroIdx);
    }
    // after it=9, accumulators live in buffer 0
    mask_kernel<<<dim3(MBLK, BB), TPB>>>(vact, mask, outA, 0);
}